// round 17
// baseline (speedup 1.0000x reference)
#include <cuda_runtime.h>

#define NROWS 2048
#define DFEAT 128
#define BLOCK 256
#define NWARP (BLOCK / 32)
#define ROWB  (DFEAT * 4)   // 512 bytes per feats row
#define STRIDE (NWARP * 4)  // columns consumed per warp per iteration round

__global__ __launch_bounds__(BLOCK) void distance_sparse_kernel(
    const float* __restrict__ feats,
    const float* __restrict__ adj,
    float* __restrict__ out)
{
    const int i    = blockIdx.x;
    const int tid  = threadIdx.x;
    const int lane = tid & 31;
    const int warp = tid >> 5;
    const int sub  = lane & 7;    // sublane within 8-lane group
    const int grp  = lane >> 3;   // group 0..3: one column per group

    __shared__ float row[NROWS];          // 8 KB dense e-row
    __shared__ int   nzoff[NROWS + 32];   // byte offsets (col*512) + pad slots
    __shared__ int   cnt;
    __shared__ float rowsum;

    // ---- earliest possible: adj-row DRAM loads (long pole at block start) ----
    const float4* arow4 = reinterpret_cast<const float4*>(adj + (size_t)i * NROWS);
    const float4 a0 = arow4[tid];
    const float4 a1 = arow4[tid + BLOCK];

    if (tid == 0) { cnt = 0; rowsum = 0.0f; }

    // vectorized smem zero: 2 STS.128 per thread
    {
        float4* row4w = reinterpret_cast<float4*>(row);
        const float4 z = make_float4(0.f, 0.f, 0.f, 0.f);
        row4w[tid]         = z;
        row4w[tid + BLOCK] = z;
    }

    // fi slices: sub + 8t, t=0..3
    const float4* fi4p = reinterpret_cast<const float4*>(feats + (size_t)i * DFEAT);
    float4 fi[4];
    #pragma unroll
    for (int t = 0; t < 4; t++) fi[t] = fi4p[sub + 8 * t];
    __syncthreads();

    // ---- Phase 1: ballot-compact nonzero columns as BYTE OFFSETS ----
    const unsigned lt = (1u << lane) - 1u;
    #pragma unroll
    for (int c = 0; c < 2; c++) {
        const float4 a = (c == 0) ? a0 : a1;
        const int t = tid + c * BLOCK;
        const unsigned b0 = __ballot_sync(0xffffffffu, a.x != 0.0f);
        const unsigned b1 = __ballot_sync(0xffffffffu, a.y != 0.0f);
        const unsigned b2 = __ballot_sync(0xffffffffu, a.z != 0.0f);
        const unsigned b3 = __ballot_sync(0xffffffffu, a.w != 0.0f);
        const int c0 = __popc(b0), c1 = __popc(b1), c2 = __popc(b2), c3 = __popc(b3);
        int base = 0;
        if (lane == 0) base = atomicAdd(&cnt, c0 + c1 + c2 + c3);
        base = __shfl_sync(0xffffffffu, base, 0);
        const int off = t * 4 * ROWB;
        if (a.x != 0.0f) nzoff[base + __popc(b0 & lt)]                = off;
        if (a.y != 0.0f) nzoff[base + c0 + __popc(b1 & lt)]           = off + ROWB;
        if (a.z != 0.0f) nzoff[base + c0 + c1 + __popc(b2 & lt)]      = off + 2 * ROWB;
        if (a.w != 0.0f) nzoff[base + c0 + c1 + c2 + __popc(b3 & lt)] = off + 3 * ROWB;
    }
    __syncthreads();
    const int m = cnt;

    // pad 32 entries with offset 0 so phase-2 reads are unpredicated
    if (tid < 32) nzoff[m + tid] = 0;
    __syncthreads();

    // ---- Phase 2: 8-lane group per column, 4 cols/iter, software pipelined,
    //      unpredicated padded loads ----
    const char* fwarp = reinterpret_cast<const char*>(feats) + sub * 16;
    float wsum = 0.0f;
    {
        int o = nzoff[warp * 4 + grp];
        float4 fa[4];
        {
            const char* p = fwarp + o;
            #pragma unroll
            for (int t = 0; t < 4; t++) fa[t] = *reinterpret_cast<const float4*>(p + t * 128);
        }

        for (int k = warp * 4; k < m; k += STRIDE) {
            // ---- prefetch next iteration (padded: safe unconditional read) ----
            const int nk = k + STRIDE + grp;
            const int o2 = nzoff[nk < m ? nk : m];   // pad slot when out of range
            const char* p2 = fwarp + o2;
            float4 fb[4];
            #pragma unroll
            for (int t = 0; t < 4; t++) fb[t] = *reinterpret_cast<const float4*>(p2 + t * 128);

            // ---- compute current iteration ----
            float s = 0.0f;
            #pragma unroll
            for (int t = 0; t < 4; t++)
                s += (fabsf(fi[t].x - fa[t].x) + fabsf(fi[t].y - fa[t].y))
                   + (fabsf(fi[t].z - fa[t].z) + fabsf(fi[t].w - fa[t].w));

            #pragma unroll
            for (int off8 = 4; off8 >= 1; off8 >>= 1)
                s += __shfl_xor_sync(0xffffffffu, s, off8);

            if (sub == 0 && (k + grp) < m) {
                const float e = __expf(-0.01f * s);
                row[o >> 9] = e;       // o = col*512
                wsum += e;
            }

            #pragma unroll
            for (int t = 0; t < 4; t++) fa[t] = fb[t];
            o = o2;
        }
    }
    // combine group leaders (lanes 0,8,16,24)
    wsum += __shfl_xor_sync(0xffffffffu, wsum, 8);
    wsum += __shfl_xor_sync(0xffffffffu, wsum, 16);
    if (lane == 0 && wsum != 0.0f) atomicAdd(&rowsum, wsum);
    __syncthreads();

    // ---- Phase 3: normalize + stream full row out ----
    const float inv = 1.0f / fmaxf(rowsum, 1e-12f);
    float4* orow4 = reinterpret_cast<float4*>(out + (size_t)i * NROWS);
    const float4* row4 = reinterpret_cast<const float4*>(row);
    #pragma unroll
    for (int c = 0; c < 2; c++) {
        const int t = tid + c * BLOCK;
        float4 v = row4[t];
        v.x *= inv; v.y *= inv; v.z *= inv; v.w *= inv;
        orow4[t] = v;
    }
}

extern "C" void kernel_launch(void* const* d_in, const int* in_sizes, int n_in,
                              void* d_out, int out_size)
{
    const float* feats = (const float*)d_in[0];
    const float* adj   = (const float*)d_in[1];
    float* out         = (float*)d_out;
    distance_sparse_kernel<<<NROWS, BLOCK>>>(feats, adj, out);
}